// round 1
// baseline (speedup 1.0000x reference)
#include <cuda_runtime.h>

#define BATCH 16
#define SEQL  2048
#define HDIM  64
#define VOC   64
#define LN_EPS 1e-5f
#define D_EPS  1e-6f

// Scratch (static device allocations are the sanctioned workaround)
__device__ float g_h[BATCH * SEQL * HDIM];   // post-LN hidden states
__device__ float g_rden[BATCH * SEQL];        // 1 / (||h||^2 + D_EPS)
__device__ float g_ctx[BATCH * HDIM];         // M @ q per batch

// ---------------------------------------------------------------------------
// Kernel A: h = LN(embed[seq] + MLP(embed[seq])); also rden = 1/(||h||^2+eps)
// 128 threads/block, 4 tokens processed per iteration (weights from L1).
// ---------------------------------------------------------------------------
__global__ __launch_bounds__(128) void mlp_ln_kernel(
    const int* __restrict__ seq, const float* __restrict__ embed,
    const float* __restrict__ W1, const float* __restrict__ b1,
    const float* __restrict__ W2, const float* __restrict__ b2,
    const float* __restrict__ gamma, const float* __restrict__ beta)
{
    __shared__ __align__(16) float hs[64][4];     // [i][tok]
    __shared__ __align__(16) float t1s[128][4];   // [i][tok]
    __shared__ __align__(16) float xpart[2][64][4];
    __shared__ float red[2][8];
    __shared__ float red2[2][4];

    const int tid = threadIdx.x;
    const int nQuads = (BATCH * SEQL) / 4;

    for (int q = blockIdx.x; q < nQuads; q += gridDim.x) {
        const int t0 = q * 4;

        // gather h = embed[seq] for 4 tokens (256 floats)
        for (int e = tid; e < 256; e += 128) {
            int tok = e >> 6;
            int i   = e & 63;
            int v   = seq[t0 + tok];
            hs[i][tok] = embed[v * 64 + i];
        }
        __syncthreads();

        // phase 1: t1[j] = relu(h @ W1 + b1), j = tid (128 outputs), 4 tokens
        {
            float bb = b1[tid];
            float a0 = bb, a1 = bb, a2 = bb, a3 = bb;
            #pragma unroll
            for (int i = 0; i < 64; i++) {
                float4 hv = *(const float4*)&hs[i][0];
                float  w  = W1[i * 128 + tid];
                a0 = fmaf(hv.x, w, a0);
                a1 = fmaf(hv.y, w, a1);
                a2 = fmaf(hv.z, w, a2);
                a3 = fmaf(hv.w, w, a3);
            }
            *(float4*)&t1s[tid][0] = make_float4(fmaxf(a0, 0.f), fmaxf(a1, 0.f),
                                                 fmaxf(a2, 0.f), fmaxf(a3, 0.f));
        }
        __syncthreads();

        // phase 2: ff[j] = t1 @ W2  (split i-range over two half-groups)
        {
            int j = tid & 63, half = tid >> 6;
            float a0 = 0.f, a1 = 0.f, a2 = 0.f, a3 = 0.f;
            int ibase = half * 64;
            #pragma unroll
            for (int ii = 0; ii < 64; ii++) {
                int i = ibase + ii;
                float4 tv = *(const float4*)&t1s[i][0];
                float  w  = W2[i * 64 + j];
                a0 = fmaf(tv.x, w, a0);
                a1 = fmaf(tv.y, w, a1);
                a2 = fmaf(tv.z, w, a2);
                a3 = fmaf(tv.w, w, a3);
            }
            *(float4*)&xpart[half][j][0] = make_float4(a0, a1, a2, a3);
        }
        __syncthreads();

        // LN over 64 features (threads 0..63, warps 0 and 1)
        float x0, x1, x2, x3;
        if (tid < 64) {
            int j = tid;
            float4 pa = *(const float4*)&xpart[0][j][0];
            float4 pb = *(const float4*)&xpart[1][j][0];
            float4 hv = *(const float4*)&hs[j][0];
            float bb2 = b2[j];
            x0 = hv.x + pa.x + pb.x + bb2;
            x1 = hv.y + pa.y + pb.y + bb2;
            x2 = hv.z + pa.z + pb.z + bb2;
            x3 = hv.w + pa.w + pb.w + bb2;
            float s0 = x0, s1 = x1, s2 = x2, s3 = x3;
            float q0 = x0 * x0, q1 = x1 * x1, q2 = x2 * x2, q3 = x3 * x3;
            #pragma unroll
            for (int o = 16; o > 0; o >>= 1) {
                s0 += __shfl_xor_sync(0xffffffffu, s0, o);
                s1 += __shfl_xor_sync(0xffffffffu, s1, o);
                s2 += __shfl_xor_sync(0xffffffffu, s2, o);
                s3 += __shfl_xor_sync(0xffffffffu, s3, o);
                q0 += __shfl_xor_sync(0xffffffffu, q0, o);
                q1 += __shfl_xor_sync(0xffffffffu, q1, o);
                q2 += __shfl_xor_sync(0xffffffffu, q2, o);
                q3 += __shfl_xor_sync(0xffffffffu, q3, o);
            }
            int w = tid >> 5;
            if ((tid & 31) == 0) {
                red[w][0] = s0; red[w][1] = s1; red[w][2] = s2; red[w][3] = s3;
                red[w][4] = q0; red[w][5] = q1; red[w][6] = q2; red[w][7] = q3;
            }
        }
        __syncthreads();
        if (tid < 64) {
            int j = tid;
            const float inv = 1.0f / 64.0f;
            float S0 = red[0][0] + red[1][0];
            float S1 = red[0][1] + red[1][1];
            float S2 = red[0][2] + red[1][2];
            float S3 = red[0][3] + red[1][3];
            float Q0 = red[0][4] + red[1][4];
            float Q1 = red[0][5] + red[1][5];
            float Q2 = red[0][6] + red[1][6];
            float Q3 = red[0][7] + red[1][7];
            float mu0 = S0 * inv, mu1 = S1 * inv, mu2 = S2 * inv, mu3 = S3 * inv;
            float rs0 = rsqrtf(Q0 * inv - mu0 * mu0 + LN_EPS);
            float rs1 = rsqrtf(Q1 * inv - mu1 * mu1 + LN_EPS);
            float rs2 = rsqrtf(Q2 * inv - mu2 * mu2 + LN_EPS);
            float rs3 = rsqrtf(Q3 * inv - mu3 * mu3 + LN_EPS);
            float g = gamma[j], be = beta[j];
            float y0 = (x0 - mu0) * rs0 * g + be;
            float y1 = (x1 - mu1) * rs1 * g + be;
            float y2 = (x2 - mu2) * rs2 * g + be;
            float y3 = (x3 - mu3) * rs3 * g + be;
            g_h[(t0 + 0) * 64 + j] = y0;
            g_h[(t0 + 1) * 64 + j] = y1;
            g_h[(t0 + 2) * 64 + j] = y2;
            g_h[(t0 + 3) * 64 + j] = y3;
            float z0 = y0 * y0, z1 = y1 * y1, z2 = y2 * y2, z3 = y3 * y3;
            #pragma unroll
            for (int o = 16; o > 0; o >>= 1) {
                z0 += __shfl_xor_sync(0xffffffffu, z0, o);
                z1 += __shfl_xor_sync(0xffffffffu, z1, o);
                z2 += __shfl_xor_sync(0xffffffffu, z2, o);
                z3 += __shfl_xor_sync(0xffffffffu, z3, o);
            }
            int w = tid >> 5;
            if ((tid & 31) == 0) {
                red2[w][0] = z0; red2[w][1] = z1; red2[w][2] = z2; red2[w][3] = z3;
            }
        }
        __syncthreads();
        if (tid < 4) {
            float ss = red2[0][tid] + red2[1][tid];
            g_rden[t0 + tid] = 1.0f / (ss + D_EPS);
        }
        __syncthreads();
    }
}

// ---------------------------------------------------------------------------
// Kernel B: delta-rule scan. Row-decomposed: block = (batch, 32-row half).
// 128 threads: 32 rows x 4 lanes (16 cols each). M rows live in registers.
// k staged in shared chunks of 128 steps; rden precomputed in Kernel A.
// ---------------------------------------------------------------------------
__global__ __launch_bounds__(128) void scan_kernel()
{
    __shared__ __align__(16) float kbuf[128 * 64];
    __shared__ float rbuf[128];

    const int bb      = blockIdx.x >> 1;
    const int rowBase = (blockIdx.x & 1) * 32;
    const int tid     = threadIdx.x;
    const int r       = tid >> 2;
    const int sub     = tid & 3;
    const int gr      = rowBase + r;

    float m[16];
    #pragma unroll
    for (int i = 0; i < 16; i++) m[i] = 0.f;

    const float* hb  = g_h    + bb * SEQL * 64;
    const float* rdb = g_rden + bb * SEQL;

    int done = 0;
    while (done < SEQL - 1) {
        int n = SEQL - 1 - done;
        if (n > 128) n = 128;
        __syncthreads();
        for (int e = tid * 4; e < n * 64; e += 128 * 4) {
            *(float4*)&kbuf[e] = *(const float4*)&hb[done * 64 + e];
        }
        for (int e = tid; e < n; e += 128) rbuf[e] = rdb[done + e];
        __syncthreads();

        for (int s = 0; s < n; s++) {
            const float* kp = &kbuf[s * 64 + sub * 16];
            float4 ka = *(const float4*)(kp + 0);
            float4 kb = *(const float4*)(kp + 4);
            float4 kc = *(const float4*)(kp + 8);
            float4 kd = *(const float4*)(kp + 12);
            float p0 = fmaf(m[0], ka.x, fmaf(m[1], ka.y, fmaf(m[2], ka.z, m[3] * ka.w)));
            float p1 = fmaf(m[4], kb.x, fmaf(m[5], kb.y, fmaf(m[6], kb.z, m[7] * kb.w)));
            float p2 = fmaf(m[8], kc.x, fmaf(m[9], kc.y, fmaf(m[10], kc.z, m[11] * kc.w)));
            float p3 = fmaf(m[12], kd.x, fmaf(m[13], kd.y, fmaf(m[14], kd.z, m[15] * kd.w)));
            float vp = (p0 + p1) + (p2 + p3);
            vp += __shfl_xor_sync(0xffffffffu, vp, 1);
            vp += __shfl_xor_sync(0xffffffffu, vp, 2);
            float ki = kbuf[s * 64 + gr];
            float dv = fmaf(-vp, rbuf[s], ki);
            m[0]  = fmaf(dv, ka.x, m[0]);
            m[1]  = fmaf(dv, ka.y, m[1]);
            m[2]  = fmaf(dv, ka.z, m[2]);
            m[3]  = fmaf(dv, ka.w, m[3]);
            m[4]  = fmaf(dv, kb.x, m[4]);
            m[5]  = fmaf(dv, kb.y, m[5]);
            m[6]  = fmaf(dv, kb.z, m[6]);
            m[7]  = fmaf(dv, kb.w, m[7]);
            m[8]  = fmaf(dv, kc.x, m[8]);
            m[9]  = fmaf(dv, kc.y, m[9]);
            m[10] = fmaf(dv, kc.z, m[10]);
            m[11] = fmaf(dv, kc.w, m[11]);
            m[12] = fmaf(dv, kd.x, m[12]);
            m[13] = fmaf(dv, kd.y, m[13]);
            m[14] = fmaf(dv, kd.z, m[14]);
            m[15] = fmaf(dv, kd.w, m[15]);
        }
        done += n;
    }

    // ctx = M @ q, q = h[b, L-1, :]
    const float4* qp = (const float4*)&hb[(SEQL - 1) * 64 + sub * 16];
    float4 qa = qp[0], qb = qp[1], qc = qp[2], qd = qp[3];
    float p0 = fmaf(m[0], qa.x, fmaf(m[1], qa.y, fmaf(m[2], qa.z, m[3] * qa.w)));
    float p1 = fmaf(m[4], qb.x, fmaf(m[5], qb.y, fmaf(m[6], qb.z, m[7] * qb.w)));
    float p2 = fmaf(m[8], qc.x, fmaf(m[9], qc.y, fmaf(m[10], qc.z, m[11] * qc.w)));
    float p3 = fmaf(m[12], qd.x, fmaf(m[13], qd.y, fmaf(m[14], qd.z, m[15] * qd.w)));
    float vp = (p0 + p1) + (p2 + p3);
    vp += __shfl_xor_sync(0xffffffffu, vp, 1);
    vp += __shfl_xor_sync(0xffffffffu, vp, 2);
    if (sub == 0) g_ctx[bb * 64 + gr] = vp;
}

// ---------------------------------------------------------------------------
// Kernel C: out = (ctx @ Wr + br) @ Wo + bo
// ---------------------------------------------------------------------------
__global__ __launch_bounds__(64) void head_kernel(
    const float* __restrict__ Wr, const float* __restrict__ br,
    const float* __restrict__ Wo, const float* __restrict__ bo,
    float* __restrict__ out)
{
    __shared__ float ctx_s[64];
    __shared__ float r_s[64];
    int b = blockIdx.x, j = threadIdx.x;
    ctx_s[j] = g_ctx[b * 64 + j];
    __syncthreads();
    float a = br[j];
    #pragma unroll
    for (int i = 0; i < 64; i++) a = fmaf(ctx_s[i], Wr[i * 64 + j], a);
    r_s[j] = a;
    __syncthreads();
    float o = bo[j];
    #pragma unroll
    for (int i = 0; i < 64; i++) o = fmaf(r_s[i], Wo[i * 64 + j], o);
    out[b * 64 + j] = o;
}

// ---------------------------------------------------------------------------
extern "C" void kernel_launch(void* const* d_in, const int* in_sizes, int n_in,
                              void* d_out, int out_size)
{
    const int*   seq   = (const int*)d_in[0];
    const float* embed = (const float*)d_in[1];
    const float* W1    = (const float*)d_in[2];
    const float* b1    = (const float*)d_in[3];
    const float* W2    = (const float*)d_in[4];
    const float* b2    = (const float*)d_in[5];
    const float* gamma = (const float*)d_in[6];
    const float* beta  = (const float*)d_in[7];
    const float* Wr    = (const float*)d_in[8];
    const float* br    = (const float*)d_in[9];
    const float* Wo    = (const float*)d_in[10];
    const float* bo    = (const float*)d_in[11];
    float* out = (float*)d_out;

    mlp_ln_kernel<<<296, 128>>>(seq, embed, W1, b1, W2, b2, gamma, beta);
    scan_kernel<<<32, 128>>>();
    head_kernel<<<16, 64>>>(Wr, br, Wo, bo, out);
}

// round 3
// speedup vs baseline: 5.6571x; 5.6571x over previous
#include <cuda_runtime.h>

#define LN_EPS 1e-5f
#define D_EPS  1e-6f
#define BATCH  16
#define SEQL   2048

// Scratch
__device__ float g_tab[64 * 64];   // per-token post-LN hidden vector
__device__ float g_G[64 * 64];     // Gram: G[a][c] = tab_a . tab_c
__device__ float g_TW[64 * 64];    // Tab @ Wr
__device__ float g_rneg[64];       // -1/(||tab_a||^2 + D_EPS)
__device__ float g_dneg[64];       // -(||tab_a||^2 + D_EPS)
__device__ float g_beta[BATCH * 64];

// ---------------------------------------------------------------------------
// K1: per-token table: tab[a] = LN(e_a + MLP(e_a)); also dneg/rneg.
// 64 blocks (one per token id), 128 threads.
// ---------------------------------------------------------------------------
__global__ __launch_bounds__(128) void table_kernel(
    const float* __restrict__ embed, const float* __restrict__ W1,
    const float* __restrict__ b1, const float* __restrict__ W2,
    const float* __restrict__ b2, const float* __restrict__ gamma,
    const float* __restrict__ beta)
{
    __shared__ float hs[64];
    __shared__ float t1s[128];
    __shared__ float xh[2][64];
    __shared__ float red[2][2];

    const int a = blockIdx.x, tid = threadIdx.x;
    if (tid < 64) hs[tid] = embed[a * 64 + tid];
    __syncthreads();

    // t1 = relu(h @ W1 + b1): 128 outputs, one per thread
    float acc = b1[tid];
    #pragma unroll
    for (int i = 0; i < 64; i++) acc = fmaf(hs[i], W1[i * 128 + tid], acc);
    t1s[tid] = fmaxf(acc, 0.f);
    __syncthreads();

    // ff = t1 @ W2 (+b2 later): split the 128-sum over two half-groups
    {
        int j = tid & 63, half = tid >> 6;
        float a2 = 0.f;
        #pragma unroll
        for (int ii = 0; ii < 64; ii++) {
            int i = half * 64 + ii;
            a2 = fmaf(t1s[i], W2[i * 64 + j], a2);
        }
        xh[half][j] = a2;
    }
    __syncthreads();

    float x = 0.f, y = 0.f;
    if (tid < 64) {
        x = hs[tid] + xh[0][tid] + xh[1][tid] + b2[tid];
        float s = x, q = x * x;
        #pragma unroll
        for (int o = 16; o > 0; o >>= 1) {
            s += __shfl_xor_sync(0xffffffffu, s, o);
            q += __shfl_xor_sync(0xffffffffu, q, o);
        }
        if ((tid & 31) == 0) { red[tid >> 5][0] = s; red[tid >> 5][1] = q; }
    }
    __syncthreads();
    if (tid < 64) {
        float S = red[0][0] + red[1][0];
        float Q = red[0][1] + red[1][1];
        float mu = S * (1.0f / 64.0f);
        float var = Q * (1.0f / 64.0f) - mu * mu;
        y = (x - mu) * rsqrtf(var + LN_EPS) * gamma[tid] + beta[tid];
        g_tab[a * 64 + tid] = y;
        float z = y * y;
        #pragma unroll
        for (int o = 16; o > 0; o >>= 1) z += __shfl_xor_sync(0xffffffffu, z, o);
        if ((tid & 31) == 0) red[tid >> 5][0] = z;
    }
    __syncthreads();
    if (tid == 0) {
        float ss = red[0][0] + red[1][0];
        float d = ss + D_EPS;
        g_dneg[a] = -d;
        g_rneg[a] = -1.0f / d;
    }
}

// ---------------------------------------------------------------------------
// K2: G = Tab Tab^T and TW = Tab @ Wr. 64 blocks x 64 threads.
// ---------------------------------------------------------------------------
__global__ __launch_bounds__(64) void gram_kernel(const float* __restrict__ Wr)
{
    __shared__ float T[64][65];
    const int a = blockIdx.x, t = threadIdx.x;
    for (int r = 0; r < 64; r++) T[r][t] = g_tab[r * 64 + t];
    __syncthreads();
    float g = 0.f, tw = 0.f;
    #pragma unroll
    for (int h = 0; h < 64; h++) {
        float av = T[a][h];
        g  = fmaf(av, T[t][h], g);
        tw = fmaf(av, Wr[h * 64 + t], tw);
    }
    g_G[a * 64 + t]  = g;
    g_TW[a * 64 + t] = tw;
}

// ---------------------------------------------------------------------------
// K3: token-space backward delta scan. 1 block = 1 batch; warp 0 computes,
// other warps only help fill shared then retire. Depth-2 shfl lookahead.
//   state: w[a] = Tab[a].u  (2 entries per lane, registers)
//   per step i (token v):  cm_i = fma(cm_{i-1}, nrg_i, nrA_i)
//                          s_i  = cm_i * dneg_i ; beta[v] += s_i
//                          w    = fma(cm_i, G[v,.], w)
//   where A_i = w_{i-2}[v_i] via shfl, nrA = rn*A, nrg = rn*G[v_i, v_{i-1}].
// ---------------------------------------------------------------------------
__global__ __launch_bounds__(256) void scan_kernel(const int* __restrict__ seq)
{
    __shared__ float Gsh[130 * 64];   // rows 64..129 zero (dummy-token safety)
    __shared__ int   sseq[2056];      // reversed keys + pad token 127
    __shared__ float rnsh[128];       // -r per token; 0 for tokens >= 64
    __shared__ float dnsh[128];       // -(d+eps) per token; 0 for >= 64

    const int b = blockIdx.x;
    const int tid = threadIdx.x;
    const int* sq = seq + b * SEQL;

    for (int e = tid; e < 64 * 64; e += 256) Gsh[e] = g_G[e];
    for (int e = tid; e < 66 * 64; e += 256) Gsh[64 * 64 + e] = 0.f;
    for (int e = tid; e < 128; e += 256) {
        rnsh[e] = (e < 64) ? g_rneg[e] : 0.f;
        dnsh[e] = (e < 64) ? g_dneg[e] : 0.f;
    }
    for (int e = tid; e < 2056; e += 256) sseq[e] = (e < 2047) ? sq[2046 - e] : 127;
    __syncthreads();
    if (tid >= 32) return;

    const int l  = tid;
    const int e0 = 2 * l, e1 = 2 * l + 1;
    const int vq = sq[2047];

    float w0 = Gsh[e0 * 64 + vq];
    float w1 = Gsh[e1 * 64 + vq];
    float beta0 = 0.f, beta1 = 0.f;
    float cm = 0.f;

    int   V[8];
    float A[4], NRA[4], NRG[4], DN[4], GP0[4], GP1[4], GV[4], RN[4];

    V[0] = sseq[0]; V[1] = sseq[1]; V[2] = sseq[2]; V[3] = sseq[3];

    // Prologue: A for steps 0,1 come from the initial w (no updates yet).
    {
        float ws = (V[0] & 1) ? w1 : w0;
        A[0] = __shfl_sync(0xffffffffu, ws, V[0] >> 1);
        ws = (V[1] & 1) ? w1 : w0;
        A[1] = __shfl_sync(0xffffffffu, ws, V[1] >> 1);
    }
    RN[0] = rnsh[V[0]]; RN[1] = rnsh[V[1]];
    NRA[0] = RN[0] * A[0];
    NRG[0] = 0.f;                         // no step before step 0
    DN[0]  = dnsh[V[0]];
    GP0[0] = Gsh[V[0] * 64 + e0]; GP1[0] = Gsh[V[0] * 64 + e1];
    DN[1]  = dnsh[V[1]];
    GP0[1] = Gsh[V[1] * 64 + e0]; GP1[1] = Gsh[V[1] * 64 + e1];
    GV[1]  = Gsh[V[1] * 64 + V[0]];

    // 2047 real steps + 1 dummy (token 127, rn=0 => cm=0 => harmless)
    #pragma unroll 8
    for (int i = 0; i < 2048; i++) {
        const int s0 = i & 3, s1 = (i + 1) & 3, s2 = (i + 2) & 3;
        cm = fmaf(cm, NRG[s0], NRA[s0]);
        float s = cm * DN[s0];
        int vi = V[i & 7];
        if (vi == e0) beta0 += s;
        if (vi == e1) beta1 += s;
        w0 = fmaf(cm, GP0[s0], w0);
        w1 = fmaf(cm, GP1[s0], w1);
        const int v2 = V[(i + 2) & 7];
        float ws = (v2 & 1) ? w1 : w0;
        A[s2] = __shfl_sync(0xffffffffu, ws, v2 >> 1);
        NRA[s1] = RN[s1] * A[s1];
        NRG[s1] = RN[s1] * GV[s1];
        DN[s2]  = dnsh[v2];
        GP0[s2] = Gsh[v2 * 64 + e0];
        GP1[s2] = Gsh[v2 * 64 + e1];
        GV[s2]  = Gsh[v2 * 64 + V[(i + 1) & 7]];
        RN[s2]  = rnsh[v2];
        V[(i + 4) & 7] = sseq[i + 4];
    }

    g_beta[b * 64 + e0] = beta0;
    g_beta[b * 64 + e1] = beta1;
}

// ---------------------------------------------------------------------------
// K4: out[b,:] = (beta_b @ TW + br) @ Wo + bo     (ctx@Wr folded into TW)
// ---------------------------------------------------------------------------
__global__ __launch_bounds__(64) void head_kernel(
    const float* __restrict__ br, const float* __restrict__ Wo,
    const float* __restrict__ bo, float* __restrict__ out)
{
    __shared__ float bsh[64], rsh[64];
    const int b = blockIdx.x, j = threadIdx.x;
    bsh[j] = g_beta[b * 64 + j];
    __syncthreads();
    float acc = br[j];
    #pragma unroll
    for (int a = 0; a < 64; a++) acc = fmaf(bsh[a], g_TW[a * 64 + j], acc);
    rsh[j] = acc;
    __syncthreads();
    float o = bo[j];
    #pragma unroll
    for (int k = 0; k < 64; k++) o = fmaf(rsh[k], Wo[k * 64 + j], o);
    out[b * 64 + j] = o;
}

// ---------------------------------------------------------------------------
extern "C" void kernel_launch(void* const* d_in, const int* in_sizes, int n_in,
                              void* d_out, int out_size)
{
    const int*   seq   = (const int*)d_in[0];
    const float* embed = (const float*)d_in[1];
    const float* W1    = (const float*)d_in[2];
    const float* b1    = (const float*)d_in[3];
    const float* W2    = (const float*)d_in[4];
    const float* b2    = (const float*)d_in[5];
    const float* gamma = (const float*)d_in[6];
    const float* beta  = (const float*)d_in[7];
    // d_in[8] = Wr (consumed in gram_kernel via g_TW)
    const float* Wr    = (const float*)d_in[8];
    const float* br    = (const float*)d_in[9];
    const float* Wo    = (const float*)d_in[10];
    const float* bo    = (const float*)d_in[11];
    float* out = (float*)d_out;

    table_kernel<<<64, 128>>>(embed, W1, b1, W2, b2, gamma, beta);
    gram_kernel<<<64, 64>>>(Wr);
    scan_kernel<<<16, 256>>>(seq);
    head_kernel<<<16, 64>>>(br, Wo, bo, out);
}